// round 4
// baseline (speedup 1.0000x reference)
#include <cuda_runtime.h>
#include <cstdint>

// PolyLoss single-launch, 4-way row-split version.
// B=4, K=128, C=32 (V=16), H=W=128, OFF=32.
// One block (512 threads) per (b,k) poly pair.
// tid -> (row = tid>>2, half = (tid>>1)&1, pg = tid&1).
// Each thread builds one 64-bit word of one polygon's row mask (16 edges).
// inter via shfl-xor partner exchange; packed int reduction; last-block
// threadfence reduction folds 512 partials into the scalar output.

#define NB 4
#define NK 128
#define NC 32
#define NV 16
#define NH 128
#define NW 128
#define NBLK (NB * NK)   // 512
#define NT 512

typedef unsigned long long ull;

__device__ float4 g_part[NBLK];          // x=iou*m, y=reg, z=maskf
__device__ unsigned int g_count = 0;     // reset by last block each launch

__global__ void __launch_bounds__(NT) poly_kernel(
    const float* __restrict__ output,   // (B,C,H,W)
    const int*   __restrict__ mask,     // (B,K)
    const int*   __restrict__ ind,      // (B,K)
    const float* __restrict__ target,   // (B,K,C)
    float*       __restrict__ out)
{
    const int poly = blockIdx.x;            // 0..511
    const int b = poly >> 7, k = poly & 127;
    const int tid = threadIdx.x;
    const int lane = tid & 31, wid = tid >> 5;

    __shared__ float  s_xy[64];             // [0..31]=pred, [32..63]=gt coords
    __shared__ float4 e_pk[32];             // edge: x=x1, y=y1, z=y2, w=slope
    __shared__ int    s_red[16];
    __shared__ float  s_reg;
    __shared__ bool   s_last;

    if (tid < NC) {
        int idx = ind[b * NK + k];
        s_xy[tid]      = output[((b * NC + tid) * (NH * NW)) + idx];
        s_xy[32 + tid] = target[(b * NK + k) * NC + tid];
    }
    __syncthreads();

    const float maskf = (float)mask[b * NK + k];

    // ---- edge precompute + reg-loss partial (threads 0..31) ----
    if (tid < 32) {
        const int base = (tid >> 4) << 5;   // 0 = pred, 32 = gt
        const int v  = tid & 15;
        const int v2 = (v + 1) & 15;
        float x1 = s_xy[base + 2 * v]      + 32.f;
        float y1 = s_xy[base + 2 * v + 1]  + 32.f;
        float x2 = s_xy[base + 2 * v2]     + 32.f;
        float y2 = s_xy[base + 2 * v2 + 1] + 32.f;
        float dy = y2 - y1;
        float denom = (dy == 0.f) ? 1.f : dy;
        e_pk[tid] = make_float4(x1, y1, y2, (x2 - x1) / denom);

        float d = fabsf(s_xy[tid] * maskf - s_xy[32 + tid] * maskf);
        #pragma unroll
        for (int o = 16; o; o >>= 1) d += __shfl_down_sync(0xffffffffu, d, o);
        if (tid == 0) s_reg = d;
    }
    __syncthreads();

    const int   pg    = tid & 1;            // 0 = pred, 1 = gt
    const int   half  = (tid >> 1) & 1;     // which 64-bit word
    const float py    = (float)(tid >> 2);  // raster row
    const float basef = half ? 64.f : 0.f;
    const int   ebase = pg << 4;

    ull word = 0;
    #pragma unroll
    for (int e = 0; e < 16; e++) {
        float4 E = e_pk[ebase + e];
        bool crossing = (E.y <= py) != (E.z <= py);
        float xint = fmaf(py - E.y, E.w, E.x);
        float v = fminf(fmaxf(xint - basef, 0.f), 64.f);
        int m = __float2int_ru(v);
        m = crossing ? m : 0;
        ull msk = (m >= 64) ? ~0ull : ((1ull << m) - 1ull);
        word ^= msk;
    }

    // partner (other polygon, same row & half) word
    ull other = __shfl_xor_sync(0xffffffffu, word, 1);
    int icnt = __popcll(word & other);      // counted by BOTH partners -> /2 later
    int cnt  = __popcll(word);
    int packed = icnt | (cnt << 16);        // each field sum < 2^16 over 512 threads

    #pragma unroll
    for (int o = 16; o; o >>= 1)
        packed += __shfl_down_sync(0xffffffffu, packed, o);
    if (lane == 0) s_red[wid] = packed;
    __syncthreads();

    if (tid == 0) {
        int tot = 0;
        #pragma unroll
        for (int w = 0; w < 16; w++) tot += s_red[w];
        float inter = (float)((tot & 0xFFFF) >> 1);
        float cnts  = (float)((unsigned)tot >> 16);     // cp + cg
        float un    = cnts - inter;
        float iou   = inter / (un + 1e-6f);
        g_part[poly] = make_float4(iou * maskf, s_reg, maskf, 0.f);
        __threadfence();
        unsigned int old = atomicAdd(&g_count, 1u);
        s_last = (old == NBLK - 1);
    }
    __syncthreads();

    if (s_last) {
        // final reduction over 512 partials: one per thread
        float4 p = g_part[tid];
        float a0 = p.x, a1 = p.y, a2 = p.z;
        #pragma unroll
        for (int o = 16; o; o >>= 1) {
            a0 += __shfl_down_sync(0xffffffffu, a0, o);
            a1 += __shfl_down_sync(0xffffffffu, a1, o);
            a2 += __shfl_down_sync(0xffffffffu, a2, o);
        }
        __shared__ float s_f[3][16];
        if (lane == 0) { s_f[0][wid] = a0; s_f[1][wid] = a1; s_f[2][wid] = a2; }
        __syncthreads();
        if (tid == 0) {
            float t0 = 0.f, t1 = 0.f, t2 = 0.f;
            #pragma unroll
            for (int w = 0; w < 16; w++) { t0 += s_f[0][w]; t1 += s_f[1][w]; t2 += s_f[2][w]; }
            float inv = 1.f / (t2 + 1e-6f);
            out[0] = (1.f - t0 * inv) + t1 * inv;
            g_count = 0;   // reset for next graph replay
        }
    }
}

extern "C" void kernel_launch(void* const* d_in, const int* in_sizes, int n_in,
                              void* d_out, int out_size) {
    const float* output = (const float*)d_in[0];
    const int*   mask   = (const int*)d_in[1];
    const int*   ind    = (const int*)d_in[2];
    const float* target = (const float*)d_in[3];
    float* out = (float*)d_out;

    poly_kernel<<<NBLK, NT>>>(output, mask, ind, target, out);
}

// round 6
// speedup vs baseline: 1.1642x; 1.1642x over previous
#include <cuda_runtime.h>
#include <cstdint>

// PolyLoss single-launch, pred/gt-split version.
// B=4, K=128, C=32 (V=16), H=W=128, OFF=32.
// One block (256 threads) per (b,k) poly pair.
// tid -> (row = tid>>1, pg = tid&1). Each thread rasterizes one polygon's
// full 128-bit row mask from 16 precomputed edges (x1,y1,y2,slope as float4).
// inter via shfl_xor(1) partner exchange; packed-int block reduction;
// last-block threadfence reduction folds 512 partials into the scalar out.

#define NB 4
#define NK 128
#define NC 32
#define NV 16
#define NH 128
#define NW 128
#define NBLK (NB * NK)   // 512
#define NT 256

typedef unsigned long long ull;

__device__ float4 g_part[NBLK];          // x=iou*m, y=reg, z=maskf
__device__ unsigned int g_count = 0;     // reset by last block each launch

__global__ void __launch_bounds__(NT) poly_kernel(
    const float* __restrict__ output,   // (B,C,H,W)
    const int*   __restrict__ mask,     // (B,K)
    const int*   __restrict__ ind,      // (B,K)
    const float* __restrict__ target,   // (B,K,C)
    float*       __restrict__ out)
{
    const int poly = blockIdx.x;            // 0..511
    const int b = poly >> 7, k = poly & 127;
    const int tid = threadIdx.x;
    const int lane = tid & 31, wid = tid >> 5;

    __shared__ float  s_xy[64];             // [0..31]=pred, [32..63]=gt coords
    __shared__ float4 e_pk[32];             // edge: x=x1, y=y1, z=y2, w=slope
    __shared__ int    s_red[8];
    __shared__ float  s_reg;
    __shared__ bool   s_last;

    if (tid < NC) {
        int idx = ind[b * NK + k];
        s_xy[tid]      = output[((b * NC + tid) * (NH * NW)) + idx];
        s_xy[32 + tid] = target[(b * NK + k) * NC + tid];
    }
    __syncthreads();

    const float maskf = (float)mask[b * NK + k];

    // ---- edge precompute + reg-loss partial (threads 0..31) ----
    if (tid < 32) {
        const int base = (tid >> 4) << 5;   // 0 = pred, 32 = gt
        const int v  = tid & 15;
        const int v2 = (v + 1) & 15;
        float x1 = s_xy[base + 2 * v]      + 32.f;
        float y1 = s_xy[base + 2 * v + 1]  + 32.f;
        float x2 = s_xy[base + 2 * v2]     + 32.f;
        float y2 = s_xy[base + 2 * v2 + 1] + 32.f;
        float dy = y2 - y1;
        float denom = (dy == 0.f) ? 1.f : dy;
        e_pk[tid] = make_float4(x1, y1, y2, (x2 - x1) / denom);

        float d = fabsf(s_xy[tid] * maskf - s_xy[32 + tid] * maskf);
        #pragma unroll
        for (int o = 16; o; o >>= 1) d += __shfl_down_sync(0xffffffffu, d, o);
        if (tid == 0) s_reg = d;
    }
    __syncthreads();

    const int   pg    = tid & 1;            // 0 = pred, 1 = gt
    const float py    = (float)(tid >> 1);  // raster row
    const int   ebase = pg << 4;

    ull wlo = 0, whi = 0;
    #pragma unroll
    for (int e = 0; e < 16; e++) {
        float4 E = e_pk[ebase + e];
        bool crossing = (E.y <= py) != (E.z <= py);
        float xint = fmaf(py - E.y, E.w, E.x);
        int n = __float2int_ru(fminf(fmaxf(xint, 0.f), 128.f));
        n = crossing ? n : 0;
        int m = n - 64;
        ull lo = (n >= 64) ? ~0ull : ((1ull << n) - 1ull);
        ull hi = (m > 0)   ? ((1ull << m) - 1ull) : 0ull;
        wlo ^= lo;
        whi ^= hi;
    }

    // partner (other polygon, same row) words
    ull olo = __shfl_xor_sync(0xffffffffu, wlo, 1);
    ull ohi = __shfl_xor_sync(0xffffffffu, whi, 1);
    int icnt = __popcll(wlo & olo) + __popcll(whi & ohi);   // double-counted
    int cnt  = __popcll(wlo) + __popcll(whi);
    int packed = icnt | (cnt << 16);

    #pragma unroll
    for (int o = 16; o; o >>= 1)
        packed += __shfl_down_sync(0xffffffffu, packed, o);
    if (lane == 0) s_red[wid] = packed;
    __syncthreads();

    if (tid == 0) {
        int tot = 0;
        #pragma unroll
        for (int w = 0; w < 8; w++) tot += s_red[w];
        float inter = (float)((tot & 0xFFFF) >> 1);
        float cnts  = (float)((unsigned)tot >> 16);     // cp + cg
        float un    = cnts - inter;
        float iou   = inter / (un + 1e-6f);
        g_part[poly] = make_float4(iou * maskf, s_reg, maskf, 0.f);
        __threadfence();
        unsigned int old = atomicAdd(&g_count, 1u);
        s_last = (old == NBLK - 1);
    }
    __syncthreads();

    if (s_last) {
        // final reduction over 512 partials: two per thread
        float4 p0 = g_part[tid];
        float4 p1 = g_part[tid + NT];
        float a0 = p0.x + p1.x, a1 = p0.y + p1.y, a2 = p0.z + p1.z;
        #pragma unroll
        for (int o = 16; o; o >>= 1) {
            a0 += __shfl_down_sync(0xffffffffu, a0, o);
            a1 += __shfl_down_sync(0xffffffffu, a1, o);
            a2 += __shfl_down_sync(0xffffffffu, a2, o);
        }
        __shared__ float s_f[3][8];
        if (lane == 0) { s_f[0][wid] = a0; s_f[1][wid] = a1; s_f[2][wid] = a2; }
        __syncthreads();
        if (tid == 0) {
            float t0 = 0.f, t1 = 0.f, t2 = 0.f;
            #pragma unroll
            for (int w = 0; w < 8; w++) { t0 += s_f[0][w]; t1 += s_f[1][w]; t2 += s_f[2][w]; }
            float inv = 1.f / (t2 + 1e-6f);
            out[0] = (1.f - t0 * inv) + t1 * inv;
            g_count = 0;   // reset for next graph replay
        }
    }
}

extern "C" void kernel_launch(void* const* d_in, const int* in_sizes, int n_in,
                              void* d_out, int out_size) {
    const float* output = (const float*)d_in[0];
    const int*   mask   = (const int*)d_in[1];
    const int*   ind    = (const int*)d_in[2];
    const float* target = (const float*)d_in[3];
    float* out = (float*)d_out;

    poly_kernel<<<NBLK, NT>>>(output, mask, ind, target, out);
}